// round 1
// baseline (speedup 1.0000x reference)
#include <cuda_runtime.h>
#include <math.h>

#define BB 4
#define CC 256
#define HH 128
#define WW 128
#define AA 9
#define NPOS (HH*WW)          // 16384
#define NANCH (NPOS*AA)       // 147456
#define PRE_K 600
#define POST_K 100
#define NMS_WORDS 19          // ceil(600/32)
#define BINS 4096
#define BIN_SHIFT 20
#define CAP 2048

// ---------------- scratch (device globals; no allocation allowed) ----------
__device__ __align__(16) float d_t[BB*CC*NPOS];          // conv+relu output, 64 MB
__device__ __align__(16) float d_scores[BB*NANCH];       // 2.25 MB
__device__ __align__(16) float d_deltas[BB*NANCH*4];     // 9 MB
__device__ unsigned int d_hist[BB][BINS];
__device__ int d_thrbin[BB];
__device__ int d_candcnt[BB];
__device__ unsigned long long d_cand[BB][CAP];
__device__ __align__(16) float d_boxes[BB][PRE_K*4];
__device__ unsigned int d_mask[BB][PRE_K*NMS_WORDS];

// anchor half-sizes, a = scale_idx*3 + ratio_idx, computed in double then fp32
__constant__ float c_hw[9] = {
    45.25483399593904f,  64.0f, 90.50966799187808f,
    90.50966799187808f, 128.0f, 181.01933598375617f,
    181.01933598375617f,256.0f, 362.03867196751233f};
__constant__ float c_hh[9] = {
    90.50966799187808f,  64.0f, 45.25483399593904f,
    181.01933598375617f,128.0f, 90.50966799187808f,
    362.03867196751233f,256.0f, 181.01933598375617f};

// ---------------- K1: 3x3 conv (256->256) + ReLU, fp32 ---------------------
// grid (8,8,16): x=tile-x(16px), y=tile-y(16px), z = b*4 + co_group(64ch)
// block 256 threads: thread = pg(0..31)*8 + cg(0..7)
//   pixels: row pr=pg>>1, col base pc=(pg&1)*8 -> 8 consecutive x
//   channels: cg*8 .. cg*8+7
__global__ __launch_bounds__(256, 2)
void k_conv3(const float* __restrict__ f, const float* __restrict__ w,
             const float* __restrict__ bias)
{
    __shared__ float sA[8][18][18];   // [ci][y][x] input halo tile
    __shared__ float sB[72][68];      // [(ci*9+k)][co], padded for banks/align

    const int tid = threadIdx.x;
    const int pg = tid >> 3, cg = tid & 7;
    const int pr = pg >> 1, pc = (pg & 1) * 8;
    const int b = blockIdx.z >> 2;
    const int co_base = (blockIdx.z & 3) * 64;
    const int x0 = blockIdx.x * 16, y0 = blockIdx.y * 16;

    float acc[8][8];   // [pixel m][co j]
    #pragma unroll
    for (int m = 0; m < 8; m++)
        #pragma unroll
        for (int j = 0; j < 8; j++) acc[m][j] = 0.f;

    for (int cb = 0; cb < 256; cb += 8) {
        // load input halo tile: 8ci x 18 x 18
        for (int e = tid; e < 8*18*18; e += 256) {
            int ci = e / 324; int rem = e - ci*324;
            int yy = rem / 18; int xx = rem - yy*18;
            int gy = y0 + yy - 1, gx = x0 + xx - 1;
            float v = 0.f;
            if (gy >= 0 && gy < 128 && gx >= 0 && gx < 128)
                v = f[((b*256 + cb + ci)*128 + gy)*128 + gx];
            sA[ci][yy][xx] = v;
        }
        // load weights: 64co x 72 contiguous floats each (coalesced in gmem)
        for (int e = tid; e < 72*64; e += 256) {
            int co = e / 72; int r = e - co*72;
            sB[r][co] = w[(co_base + co)*2304 + cb*9 + r];
        }
        __syncthreads();

        #pragma unroll
        for (int ci = 0; ci < 8; ci++) {
            #pragma unroll
            for (int ky = 0; ky < 3; ky++) {
                float a[10];
                #pragma unroll
                for (int m = 0; m < 10; m++) a[m] = sA[ci][pr + ky][pc + m];
                #pragma unroll
                for (int kx = 0; kx < 3; kx++) {
                    const int kk = ci*9 + ky*3 + kx;
                    const float4 b0 = *(const float4*)&sB[kk][cg*8];
                    const float4 b1 = *(const float4*)&sB[kk][cg*8 + 4];
                    const float bv[8] = {b0.x,b0.y,b0.z,b0.w,b1.x,b1.y,b1.z,b1.w};
                    #pragma unroll
                    for (int m = 0; m < 8; m++) {
                        const float av = a[kx + m];
                        #pragma unroll
                        for (int j = 0; j < 8; j++) acc[m][j] += av * bv[j];
                    }
                }
            }
        }
        __syncthreads();
    }

    #pragma unroll
    for (int j = 0; j < 8; j++) {
        const int co = co_base + cg*8 + j;
        const float bv = bias[co];
        #pragma unroll
        for (int m = 0; m < 8; m++) {
            float v = acc[m][j] + bv;
            v = fmaxf(v, 0.f);
            d_t[((b*256 + co)*128 + (y0 + pr))*128 + (x0 + pc + m)] = v;
        }
    }
}

// ---------------- K2: 1x1 heads (cls 9ch + bbox 36ch) ----------------------
// grid (64, 4): 256 pixels per block, blockIdx.y = image
__global__ __launch_bounds__(256)
void k_heads(const float* __restrict__ cls_w, const float* __restrict__ cls_b,
             const float* __restrict__ bbox_w, const float* __restrict__ bbox_b)
{
    __shared__ float swc[9][256];
    __shared__ float swb[36][256];
    __shared__ float sbc[9], sbb[36];
    const int tid = threadIdx.x;
    const int b = blockIdx.y;
    const int p = blockIdx.x * 256 + tid;

    for (int e = tid; e < 9*256; e += 256)  (&swc[0][0])[e] = cls_w[e];
    for (int e = tid; e < 36*256; e += 256) (&swb[0][0])[e] = bbox_w[e];
    if (tid < 9)  sbc[tid] = cls_b[tid];
    if (tid < 36) sbb[tid] = bbox_b[tid];
    __syncthreads();

    float as[9], ad[36];
    #pragma unroll
    for (int a = 0; a < 9; a++) as[a] = 0.f;
    #pragma unroll
    for (int d = 0; d < 36; d++) ad[d] = 0.f;

    const float* tp = d_t + (size_t)b*CC*NPOS + p;
    for (int c = 0; c < 256; c += 4) {
        const float t0 = tp[(c+0)*NPOS];
        const float t1 = tp[(c+1)*NPOS];
        const float t2 = tp[(c+2)*NPOS];
        const float t3 = tp[(c+3)*NPOS];
        #pragma unroll
        for (int a = 0; a < 9; a++) {
            const float4 wv = *(const float4*)&swc[a][c];
            as[a] += t0*wv.x + t1*wv.y + t2*wv.z + t3*wv.w;
        }
        #pragma unroll
        for (int d = 0; d < 36; d++) {
            const float4 wv = *(const float4*)&swb[d][c];
            ad[d] += t0*wv.x + t1*wv.y + t2*wv.z + t3*wv.w;
        }
    }

    float* sp = d_scores + (size_t)b*NANCH + (size_t)p*9;
    #pragma unroll
    for (int a = 0; a < 9; a++) sp[a] = as[a] + sbc[a];
    float* dp = d_deltas + ((size_t)b*NANCH + (size_t)p*9)*4;
    #pragma unroll
    for (int d = 0; d < 36; d++) dp[d] = ad[d] + sbb[d];
}

// ---------------- selection helpers ----------------------------------------
__device__ __forceinline__ unsigned fkey(float s) {
    unsigned b = __float_as_uint(s);
    return (b & 0x80000000u) ? ~b : (b | 0x80000000u);  // monotone: larger f -> larger u
}

__global__ void k_init() {
    int id = blockIdx.x * blockDim.x + threadIdx.x;
    if (id < BB*BINS) (&d_hist[0][0])[id] = 0u;
    if (id < BB) d_candcnt[id] = 0;
}

__global__ void k_hist() {
    __shared__ unsigned sh[BINS];
    const int b = blockIdx.y;
    for (int e = threadIdx.x; e < BINS; e += blockDim.x) sh[e] = 0u;
    __syncthreads();
    const float* s = d_scores + (size_t)b*NANCH;
    for (int i = blockIdx.x*blockDim.x + threadIdx.x; i < NANCH; i += gridDim.x*blockDim.x)
        atomicAdd(&sh[fkey(s[i]) >> BIN_SHIFT], 1u);
    __syncthreads();
    for (int e = threadIdx.x; e < BINS; e += blockDim.x)
        if (sh[e]) atomicAdd(&d_hist[b][e], sh[e]);
}

// suffix-sum over 4096 bins (iterative doubling), pick highest bin with cum>=600
__global__ __launch_bounds__(1024) void k_thresh() {
    __shared__ unsigned suf[BINS + 1];
    const int tid = threadIdx.x;
    for (int b = 0; b < BB; b++) {
        for (int e = tid; e < BINS; e += 1024) suf[e] = d_hist[b][e];
        if (tid == 0) suf[BINS] = 0u;
        __syncthreads();
        for (int off = 1; off < BINS; off <<= 1) {
            unsigned add[4];
            #pragma unroll
            for (int q = 0; q < 4; q++) {
                int i = tid + q*1024;
                add[q] = (i + off <= BINS) ? suf[i + off] : 0u;
            }
            __syncthreads();
            #pragma unroll
            for (int q = 0; q < 4; q++) suf[tid + q*1024] += add[q];
            __syncthreads();
        }
        #pragma unroll
        for (int q = 0; q < 4; q++) {
            int i = tid + q*1024;
            if (i < BINS && suf[i] >= PRE_K && suf[i+1] < PRE_K) d_thrbin[b] = i;
        }
        __syncthreads();
    }
}

__global__ void k_compact() {
    const int b = blockIdx.y;
    const int T = d_thrbin[b];
    const float* s = d_scores + (size_t)b*NANCH;
    for (unsigned i = blockIdx.x*blockDim.x + threadIdx.x; i < NANCH; i += gridDim.x*blockDim.x) {
        unsigned u = fkey(s[i]);
        if ((int)(u >> BIN_SHIFT) >= T) {
            int pos = atomicAdd(&d_candcnt[b], 1);
            if (pos < CAP)
                d_cand[b][pos] = ((unsigned long long)u << 32) | (unsigned)(~i);
        }
    }
}

__device__ __forceinline__ float read_dim(const void* p) {
    int i = *(const int*)p;                 // robust to int32 or float32 storage
    float f = __int_as_float(i);
    return (i > 0 && i < (1 << 20)) ? (float)i : f;
}

// per-image: bitonic sort candidates desc by (score, then lower idx), decode top-600
__global__ __launch_bounds__(1024) void k_sortdecode(const void* ph, const void* pw) {
    __shared__ unsigned long long key[CAP];
    const int b = blockIdx.x;
    const int tid = threadIdx.x;
    int n = d_candcnt[b]; if (n > CAP) n = CAP;
    for (int e = tid; e < CAP; e += 1024) key[e] = (e < n) ? d_cand[b][e] : 0ULL;
    __syncthreads();

    for (int k = 2; k <= CAP; k <<= 1) {
        for (int j = k >> 1; j > 0; j >>= 1) {
            const int t = tid;                     // CAP/2 == 1024 pairs
            const int i = ((t & ~(j - 1)) << 1) | (t & (j - 1));
            const int ixj = i | j;
            unsigned long long a = key[i], c = key[ixj];
            const bool up = ((i & k) == 0);        // descending overall
            if (up ? (a < c) : (a > c)) { key[i] = c; key[ixj] = a; }
            __syncthreads();
        }
    }

    if (tid < PRE_K) {
        const float img_h = read_dim(ph);
        const float img_w = read_dim(pw);
        const unsigned idx = ~(unsigned)(key[tid] & 0xFFFFFFFFULL);
        const int p = idx / 9, a = idx - 9*p;
        const float gx = (float)(p & 127) * 16.0f;
        const float gy = (float)(p >> 7) * 16.0f;
        const float hw = c_hw[a], hh = c_hh[a];
        // replicate reference arithmetic exactly
        const float x1 = gx - hw, y1 = gy - hh, x2 = gx + hw, y2 = gy + hh;
        const float w = x2 - x1, h = y2 - y1;
        const float cx = x1 + 0.5f*w, cy = y1 + 0.5f*h;
        const float4 dd = *(const float4*)&d_deltas[((size_t)b*NANCH + idx)*4];
        const float pcx = cx + dd.x * w;
        const float pcy = cy + dd.y * h;
        const float pw2 = w * expf(dd.z);
        const float ph2 = h * expf(dd.w);
        float4 o;
        o.x = fminf(fmaxf(pcx - 0.5f*pw2, 0.f), img_w);
        o.y = fminf(fmaxf(pcy - 0.5f*ph2, 0.f), img_h);
        o.z = fminf(fmaxf(pcx + 0.5f*pw2, 0.f), img_w);
        o.w = fminf(fmaxf(pcy + 0.5f*ph2, 0.f), img_h);
        *(float4*)&d_boxes[b][tid*4] = o;
    }
}

// 600x600 IoU suppression bitmask (j>i direction), one 32-bit word per thread
__global__ void k_mask() {
    const int id = blockIdx.x*blockDim.x + threadIdx.x;
    const int b = blockIdx.y;
    if (id >= PRE_K*NMS_WORDS) return;
    const int i = id / NMS_WORDS, wrd = id - i*NMS_WORDS;
    const float4 bi = *(const float4*)&d_boxes[b][i*4];
    const float areai = (bi.z - bi.x) * (bi.w - bi.y);
    unsigned m = 0u;
    const int j0 = wrd * 32;
    #pragma unroll 4
    for (int jj = 0; jj < 32; jj++) {
        const int j = j0 + jj;
        if (j > i && j < PRE_K) {
            const float4 bj = *(const float4*)&d_boxes[b][j*4];
            const float areaj = (bj.z - bj.x) * (bj.w - bj.y);
            const float xx1 = fmaxf(bi.x, bj.x), yy1 = fmaxf(bi.y, bj.y);
            const float xx2 = fminf(bi.z, bj.z), yy2 = fminf(bi.w, bj.w);
            const float inter = fmaxf(xx2 - xx1, 0.f) * fmaxf(yy2 - yy1, 0.f);
            const float iou = inter / (areai + areaj - inter);
            if (iou > 0.7f) m |= (1u << jj);
        }
    }
    d_mask[b][id] = m;
}

// serial suppression pass (single warp) + emit first 100 kept boxes
__global__ __launch_bounds__(128) void k_nms_out(float* __restrict__ out) {
    __shared__ unsigned smask[PRE_K*NMS_WORDS];
    __shared__ unsigned skeep[NMS_WORDS];
    __shared__ int s_sel[POST_K];
    __shared__ int s_cnt;
    const int b = blockIdx.x;
    const int tid = threadIdx.x;
    for (int e = tid; e < PRE_K*NMS_WORDS; e += 128) smask[e] = d_mask[b][e];
    __syncthreads();

    if (tid < 32) {
        unsigned rm = 0u;   // lane l (<19) owns removed-word l
        for (int i = 0; i < PRE_K; i++) {
            const unsigned wb = __shfl_sync(0xFFFFFFFFu, rm, i >> 5);
            if (!((wb >> (i & 31)) & 1u)) {
                if (tid < NMS_WORDS) rm |= smask[i*NMS_WORDS + tid];
            }
        }
        if (tid < NMS_WORDS) skeep[tid] = rm;
    }
    __syncthreads();
    if (tid == 0) {
        int cnt = 0;
        for (int j = 0; j < PRE_K && cnt < POST_K; j++)
            if (!((skeep[j >> 5] >> (j & 31)) & 1u)) s_sel[cnt++] = j;
        s_cnt = cnt;
    }
    __syncthreads();
    const int cnt = s_cnt;
    for (int k = tid; k < POST_K; k += 128) {
        float4 v = make_float4(0.f, 0.f, 0.f, 0.f);
        if (k < cnt) v = *(const float4*)&d_boxes[b][s_sel[k]*4];
        *(float4*)&out[(b*POST_K + k)*4] = v;
    }
}

// ---------------- launch ----------------------------------------------------
extern "C" void kernel_launch(void* const* d_in, const int* in_sizes, int n_in,
                              void* d_out, int out_size)
{
    const float* feats  = (const float*)d_in[0];
    const float* conv_w = (const float*)d_in[1];
    const float* conv_b = (const float*)d_in[2];
    const float* cls_w  = (const float*)d_in[3];
    const float* cls_b  = (const float*)d_in[4];
    const float* bbox_w = (const float*)d_in[5];
    const float* bbox_b = (const float*)d_in[6];
    const void*  ih     = d_in[7];
    const void*  iw     = d_in[8];

    k_init<<<64, 256>>>();
    k_conv3<<<dim3(8, 8, 16), 256>>>(feats, conv_w, conv_b);
    k_heads<<<dim3(64, 4), 256>>>(cls_w, cls_b, bbox_w, bbox_b);
    k_hist<<<dim3(64, 4), 256>>>();
    k_thresh<<<1, 1024>>>();
    k_compact<<<dim3(64, 4), 256>>>();
    k_sortdecode<<<4, 1024>>>(ih, iw);
    k_mask<<<dim3((PRE_K*NMS_WORDS + 255)/256, 4), 256>>>();
    k_nms_out<<<4, 128>>>((float*)d_out);
}

// round 2
// speedup vs baseline: 1.5288x; 1.5288x over previous
#include <cuda_runtime.h>
#include <math.h>

#define BB 4
#define CC 256
#define HH 128
#define WW 128
#define AA 9
#define NPOS (HH*WW)          // 16384
#define NANCH (NPOS*AA)       // 147456
#define PRE_K 600
#define POST_K 100
#define NMS_WORDS 19          // ceil(600/32)
#define BINS 4096
#define BIN_SHIFT 20
#define CAP 2048

typedef unsigned long long u64;

// ---------------- scratch (device globals; no allocation allowed) ----------
__device__ __align__(16) float d_t[BB*CC*NPOS];          // conv+relu output, 64 MB
__device__ __align__(16) float d_scores[BB*NANCH];       // 2.25 MB
__device__ __align__(16) float d_deltas[BB*NANCH*4];     // 9 MB
__device__ unsigned int d_hist[BB][BINS];
__device__ int d_thrbin[BB];
__device__ int d_candcnt[BB];
__device__ unsigned long long d_cand[BB][CAP];
__device__ __align__(16) float d_boxes[BB][PRE_K*4];
__device__ unsigned int d_mask[BB][PRE_K*NMS_WORDS];

// anchor half-sizes, a = scale_idx*3 + ratio_idx, computed in double then fp32
__constant__ float c_hw[9] = {
    45.25483399593904f,  64.0f, 90.50966799187808f,
    90.50966799187808f, 128.0f, 181.01933598375617f,
    181.01933598375617f,256.0f, 362.03867196751233f};
__constant__ float c_hh[9] = {
    90.50966799187808f,  64.0f, 45.25483399593904f,
    181.01933598375617f,128.0f, 90.50966799187808f,
    362.03867196751233f,256.0f, 181.01933598375617f};

// ---------------- packed f32x2 helpers (Blackwell) --------------------------
__device__ __forceinline__ u64 pack2(float x) {
    u64 r;
    asm("mov.b64 %0, {%1, %1};" : "=l"(r) : "f"(x));
    return r;
}
__device__ __forceinline__ void fma2(u64& d, u64 a, u64 b) {
    asm("fma.rn.f32x2 %0, %1, %2, %0;" : "+l"(d) : "l"(a), "l"(b));
}
__device__ __forceinline__ void unpack2(u64 a, float& lo, float& hi) {
    asm("mov.b64 {%0, %1}, %2;" : "=f"(lo), "=f"(hi) : "l"(a));
}

// ---------------- K1: 3x3 conv (256->256) + ReLU, fp32 via f32x2 -----------
// grid (8,8,16): x=tile-x(16px), y=tile-y(16px), z = b*4 + co_group(64ch)
// block 256 threads: thread = pg(0..31)*8 + cg(0..7)
//   pixels: row pr=pg>>1, col base pc=(pg&1)*8 -> 8 consecutive x
//   channels: co pairs cg*8 .. cg*8+7 (4 packed pairs)
__global__ __launch_bounds__(256, 2)
void k_conv3(const float* __restrict__ f, const float* __restrict__ w,
             const float* __restrict__ bias)
{
    __shared__ __align__(16) float sA[8][18][18];   // [ci][y][x] input halo tile
    __shared__ __align__(16) float sB[72][68];      // [(ci*9+k)][co], 272B row stride

    const int tid = threadIdx.x;
    const int pg = tid >> 3, cg = tid & 7;
    const int pr = pg >> 1, pc = (pg & 1) * 8;
    const int b = blockIdx.z >> 2;
    const int co_base = (blockIdx.z & 3) * 64;
    const int x0 = blockIdx.x * 16, y0 = blockIdx.y * 16;

    u64 acc2[8][4];   // [pixel m][co pair jp] : 2 fp32 lanes each
    #pragma unroll
    for (int m = 0; m < 8; m++)
        #pragma unroll
        for (int jp = 0; jp < 4; jp++) acc2[m][jp] = 0ULL;

    for (int cb = 0; cb < 256; cb += 8) {
        // load input halo tile: 8ci x 18 x 18
        for (int e = tid; e < 8*18*18; e += 256) {
            int ci = e / 324; int rem = e - ci*324;
            int yy = rem / 18; int xx = rem - yy*18;
            int gy = y0 + yy - 1, gx = x0 + xx - 1;
            float v = 0.f;
            if (gy >= 0 && gy < 128 && gx >= 0 && gx < 128)
                v = f[((b*256 + cb + ci)*128 + gy)*128 + gx];
            sA[ci][yy][xx] = v;
        }
        // load weights: 64co x 72 contiguous floats each (coalesced in gmem)
        for (int e = tid; e < 72*64; e += 256) {
            int co = e / 72; int r = e - co*72;
            sB[r][co] = w[(co_base + co)*2304 + cb*9 + r];
        }
        __syncthreads();

        #pragma unroll
        for (int ci = 0; ci < 8; ci++) {
            #pragma unroll
            for (int ky = 0; ky < 3; ky++) {
                u64 aw[10];
                #pragma unroll
                for (int m = 0; m < 10; m++) aw[m] = pack2(sA[ci][pr + ky][pc + m]);
                #pragma unroll
                for (int kx = 0; kx < 3; kx++) {
                    const int kk = ci*9 + ky*3 + kx;
                    const ulonglong2 b01 = *(const ulonglong2*)&sB[kk][cg*8];
                    const ulonglong2 b23 = *(const ulonglong2*)&sB[kk][cg*8 + 4];
                    #pragma unroll
                    for (int m = 0; m < 8; m++) {
                        fma2(acc2[m][0], aw[kx + m], b01.x);
                        fma2(acc2[m][1], aw[kx + m], b01.y);
                        fma2(acc2[m][2], aw[kx + m], b23.x);
                        fma2(acc2[m][3], aw[kx + m], b23.y);
                    }
                }
            }
        }
        __syncthreads();
    }

    // epilogue: unpack, +bias, relu, vectorized store (per co: 8 consecutive x)
    #pragma unroll
    for (int jp = 0; jp < 4; jp++) {
        const int co0 = co_base + cg*8 + jp*2;
        const float b0 = bias[co0], b1 = bias[co0 + 1];
        float v0[8], v1[8];
        #pragma unroll
        for (int m = 0; m < 8; m++) {
            float lo, hi;
            unpack2(acc2[m][jp], lo, hi);
            v0[m] = fmaxf(lo + b0, 0.f);
            v1[m] = fmaxf(hi + b1, 0.f);
        }
        float* p0 = &d_t[((b*256 + co0)*128 + (y0 + pr))*128 + (x0 + pc)];
        float* p1 = p0 + NPOS;
        *(float4*)p0       = make_float4(v0[0], v0[1], v0[2], v0[3]);
        *(float4*)(p0 + 4) = make_float4(v0[4], v0[5], v0[6], v0[7]);
        *(float4*)p1       = make_float4(v1[0], v1[1], v1[2], v1[3]);
        *(float4*)(p1 + 4) = make_float4(v1[4], v1[5], v1[6], v1[7]);
    }
}

// ---------------- K2: 1x1 heads (cls 9ch + bbox 36ch) ----------------------
// grid (64, 4): 256 pixels per block, blockIdx.y = image
__global__ __launch_bounds__(256)
void k_heads(const float* __restrict__ cls_w, const float* __restrict__ cls_b,
             const float* __restrict__ bbox_w, const float* __restrict__ bbox_b)
{
    __shared__ float swc[9][256];
    __shared__ float swb[36][256];
    __shared__ float sbc[9], sbb[36];
    const int tid = threadIdx.x;
    const int b = blockIdx.y;
    const int p = blockIdx.x * 256 + tid;

    for (int e = tid; e < 9*256; e += 256)  (&swc[0][0])[e] = cls_w[e];
    for (int e = tid; e < 36*256; e += 256) (&swb[0][0])[e] = bbox_w[e];
    if (tid < 9)  sbc[tid] = cls_b[tid];
    if (tid < 36) sbb[tid] = bbox_b[tid];
    __syncthreads();

    float as[9], ad[36];
    #pragma unroll
    for (int a = 0; a < 9; a++) as[a] = 0.f;
    #pragma unroll
    for (int d = 0; d < 36; d++) ad[d] = 0.f;

    const float* tp = d_t + (size_t)b*CC*NPOS + p;
    for (int c = 0; c < 256; c += 4) {
        const float t0 = tp[(c+0)*NPOS];
        const float t1 = tp[(c+1)*NPOS];
        const float t2 = tp[(c+2)*NPOS];
        const float t3 = tp[(c+3)*NPOS];
        #pragma unroll
        for (int a = 0; a < 9; a++) {
            const float4 wv = *(const float4*)&swc[a][c];
            as[a] += t0*wv.x + t1*wv.y + t2*wv.z + t3*wv.w;
        }
        #pragma unroll
        for (int d = 0; d < 36; d++) {
            const float4 wv = *(const float4*)&swb[d][c];
            ad[d] += t0*wv.x + t1*wv.y + t2*wv.z + t3*wv.w;
        }
    }

    float* sp = d_scores + (size_t)b*NANCH + (size_t)p*9;
    #pragma unroll
    for (int a = 0; a < 9; a++) sp[a] = as[a] + sbc[a];
    float* dp = d_deltas + ((size_t)b*NANCH + (size_t)p*9)*4;
    #pragma unroll
    for (int d = 0; d < 36; d++) dp[d] = ad[d] + sbb[d];
}

// ---------------- selection helpers ----------------------------------------
__device__ __forceinline__ unsigned fkey(float s) {
    unsigned b = __float_as_uint(s);
    return (b & 0x80000000u) ? ~b : (b | 0x80000000u);  // monotone: larger f -> larger u
}

__global__ void k_init() {
    int id = blockIdx.x * blockDim.x + threadIdx.x;
    if (id < BB*BINS) (&d_hist[0][0])[id] = 0u;
    if (id < BB) d_candcnt[id] = 0;
}

__global__ void k_hist() {
    __shared__ unsigned sh[BINS];
    const int b = blockIdx.y;
    for (int e = threadIdx.x; e < BINS; e += blockDim.x) sh[e] = 0u;
    __syncthreads();
    const float* s = d_scores + (size_t)b*NANCH;
    for (int i = blockIdx.x*blockDim.x + threadIdx.x; i < NANCH; i += gridDim.x*blockDim.x)
        atomicAdd(&sh[fkey(s[i]) >> BIN_SHIFT], 1u);
    __syncthreads();
    for (int e = threadIdx.x; e < BINS; e += blockDim.x)
        if (sh[e]) atomicAdd(&d_hist[b][e], sh[e]);
}

// suffix-sum over 4096 bins (iterative doubling), pick highest bin with cum>=600
__global__ __launch_bounds__(1024) void k_thresh() {
    __shared__ unsigned suf[BINS + 1];
    const int tid = threadIdx.x;
    const int b = blockIdx.x;
    for (int e = tid; e < BINS; e += 1024) suf[e] = d_hist[b][e];
    if (tid == 0) suf[BINS] = 0u;
    __syncthreads();
    for (int off = 1; off < BINS; off <<= 1) {
        unsigned add[4];
        #pragma unroll
        for (int q = 0; q < 4; q++) {
            int i = tid + q*1024;
            add[q] = (i + off <= BINS) ? suf[i + off] : 0u;
        }
        __syncthreads();
        #pragma unroll
        for (int q = 0; q < 4; q++) suf[tid + q*1024] += add[q];
        __syncthreads();
    }
    #pragma unroll
    for (int q = 0; q < 4; q++) {
        int i = tid + q*1024;
        if (i < BINS && suf[i] >= PRE_K && suf[i+1] < PRE_K) d_thrbin[b] = i;
    }
}

__global__ void k_compact() {
    const int b = blockIdx.y;
    const int T = d_thrbin[b];
    const float* s = d_scores + (size_t)b*NANCH;
    for (unsigned i = blockIdx.x*blockDim.x + threadIdx.x; i < NANCH; i += gridDim.x*blockDim.x) {
        unsigned u = fkey(s[i]);
        if ((int)(u >> BIN_SHIFT) >= T) {
            int pos = atomicAdd(&d_candcnt[b], 1);
            if (pos < CAP)
                d_cand[b][pos] = ((unsigned long long)u << 32) | (unsigned)(~i);
        }
    }
}

__device__ __forceinline__ float read_dim(const void* p) {
    int i = *(const int*)p;                 // robust to int32 or float32 storage
    float f = __int_as_float(i);
    return (i > 0 && i < (1 << 20)) ? (float)i : f;
}

// per-image: bitonic sort candidates desc by (score, then lower idx), decode top-600
__global__ __launch_bounds__(1024) void k_sortdecode(const void* ph, const void* pw) {
    __shared__ unsigned long long key[CAP];
    const int b = blockIdx.x;
    const int tid = threadIdx.x;
    int n = d_candcnt[b]; if (n > CAP) n = CAP;
    for (int e = tid; e < CAP; e += 1024) key[e] = (e < n) ? d_cand[b][e] : 0ULL;
    __syncthreads();

    for (int k = 2; k <= CAP; k <<= 1) {
        for (int j = k >> 1; j > 0; j >>= 1) {
            const int t = tid;                     // CAP/2 == 1024 pairs
            const int i = ((t & ~(j - 1)) << 1) | (t & (j - 1));
            const int ixj = i | j;
            unsigned long long a = key[i], c = key[ixj];
            const bool up = ((i & k) == 0);        // descending overall
            if (up ? (a < c) : (a > c)) { key[i] = c; key[ixj] = a; }
            __syncthreads();
        }
    }

    if (tid < PRE_K) {
        const float img_h = read_dim(ph);
        const float img_w = read_dim(pw);
        const unsigned idx = ~(unsigned)(key[tid] & 0xFFFFFFFFULL);
        const int p = idx / 9, a = idx - 9*p;
        const float gx = (float)(p & 127) * 16.0f;
        const float gy = (float)(p >> 7) * 16.0f;
        const float hw = c_hw[a], hh = c_hh[a];
        // replicate reference arithmetic exactly
        const float x1 = gx - hw, y1 = gy - hh, x2 = gx + hw, y2 = gy + hh;
        const float w = x2 - x1, h = y2 - y1;
        const float cx = x1 + 0.5f*w, cy = y1 + 0.5f*h;
        const float4 dd = *(const float4*)&d_deltas[((size_t)b*NANCH + idx)*4];
        const float pcx = cx + dd.x * w;
        const float pcy = cy + dd.y * h;
        const float pw2 = w * expf(dd.z);
        const float ph2 = h * expf(dd.w);
        float4 o;
        o.x = fminf(fmaxf(pcx - 0.5f*pw2, 0.f), img_w);
        o.y = fminf(fmaxf(pcy - 0.5f*ph2, 0.f), img_h);
        o.z = fminf(fmaxf(pcx + 0.5f*pw2, 0.f), img_w);
        o.w = fminf(fmaxf(pcy + 0.5f*ph2, 0.f), img_h);
        *(float4*)&d_boxes[b][tid*4] = o;
    }
}

// 600x600 IoU suppression bitmask (j>i direction), one 32-bit word per thread
__global__ void k_mask() {
    const int id = blockIdx.x*blockDim.x + threadIdx.x;
    const int b = blockIdx.y;
    if (id >= PRE_K*NMS_WORDS) return;
    const int i = id / NMS_WORDS, wrd = id - i*NMS_WORDS;
    const float4 bi = *(const float4*)&d_boxes[b][i*4];
    const float areai = (bi.z - bi.x) * (bi.w - bi.y);
    unsigned m = 0u;
    const int j0 = wrd * 32;
    #pragma unroll 4
    for (int jj = 0; jj < 32; jj++) {
        const int j = j0 + jj;
        if (j > i && j < PRE_K) {
            const float4 bj = *(const float4*)&d_boxes[b][j*4];
            const float areaj = (bj.z - bj.x) * (bj.w - bj.y);
            const float xx1 = fmaxf(bi.x, bj.x), yy1 = fmaxf(bi.y, bj.y);
            const float xx2 = fminf(bi.z, bj.z), yy2 = fminf(bi.w, bj.w);
            const float inter = fmaxf(xx2 - xx1, 0.f) * fmaxf(yy2 - yy1, 0.f);
            const float iou = inter / (areai + areaj - inter);
            if (iou > 0.7f) m |= (1u << jj);
        }
    }
    d_mask[b][id] = m;
}

// serial suppression pass (single warp) + emit first 100 kept boxes
__global__ __launch_bounds__(128) void k_nms_out(float* __restrict__ out) {
    __shared__ unsigned smask[PRE_K*NMS_WORDS];
    __shared__ unsigned skeep[NMS_WORDS];
    __shared__ int s_sel[POST_K];
    __shared__ int s_cnt;
    const int b = blockIdx.x;
    const int tid = threadIdx.x;
    for (int e = tid; e < PRE_K*NMS_WORDS; e += 128) smask[e] = d_mask[b][e];
    __syncthreads();

    if (tid < 32) {
        unsigned rm = 0u;   // lane l (<19) owns removed-word l
        for (int i = 0; i < PRE_K; i++) {
            const unsigned wb = __shfl_sync(0xFFFFFFFFu, rm, i >> 5);
            if (!((wb >> (i & 31)) & 1u)) {
                if (tid < NMS_WORDS) rm |= smask[i*NMS_WORDS + tid];
            }
        }
        if (tid < NMS_WORDS) skeep[tid] = rm;
    }
    __syncthreads();
    if (tid == 0) {
        int cnt = 0;
        for (int j = 0; j < PRE_K && cnt < POST_K; j++)
            if (!((skeep[j >> 5] >> (j & 31)) & 1u)) s_sel[cnt++] = j;
        s_cnt = cnt;
    }
    __syncthreads();
    const int cnt = s_cnt;
    for (int k = tid; k < POST_K; k += 128) {
        float4 v = make_float4(0.f, 0.f, 0.f, 0.f);
        if (k < cnt) v = *(const float4*)&d_boxes[b][s_sel[k]*4];
        *(float4*)&out[(b*POST_K + k)*4] = v;
    }
}

// ---------------- launch ----------------------------------------------------
extern "C" void kernel_launch(void* const* d_in, const int* in_sizes, int n_in,
                              void* d_out, int out_size)
{
    const float* feats  = (const float*)d_in[0];
    const float* conv_w = (const float*)d_in[1];
    const float* conv_b = (const float*)d_in[2];
    const float* cls_w  = (const float*)d_in[3];
    const float* cls_b  = (const float*)d_in[4];
    const float* bbox_w = (const float*)d_in[5];
    const float* bbox_b = (const float*)d_in[6];
    const void*  ih     = d_in[7];
    const void*  iw     = d_in[8];

    k_init<<<64, 256>>>();
    k_conv3<<<dim3(8, 8, 16), 256>>>(feats, conv_w, conv_b);
    k_heads<<<dim3(64, 4), 256>>>(cls_w, cls_b, bbox_w, bbox_b);
    k_hist<<<dim3(64, 4), 256>>>();
    k_thresh<<<4, 1024>>>();
    k_compact<<<dim3(64, 4), 256>>>();
    k_sortdecode<<<4, 1024>>>(ih, iw);
    k_mask<<<dim3((PRE_K*NMS_WORDS + 255)/256, 4), 256>>>();
    k_nms_out<<<4, 128>>>((float*)d_out);
}

// round 5
// speedup vs baseline: 1.6709x; 1.0930x over previous
#include <cuda_runtime.h>
#include <math.h>
#include <stdint.h>

#define BB 4
#define CC 256
#define HH 128
#define WW 128
#define AA 9
#define NPOS (HH*WW)          // 16384
#define NANCH (NPOS*AA)       // 147456
#define PRE_K 600
#define POST_K 100
#define NMS_WORDS 19          // ceil(600/32)
#define BINS 4096
#define BIN_SHIFT 20
#define CAP 2048

typedef unsigned long long u64;

// ---------------- scratch (device globals; no allocation allowed) ----------
__device__ __align__(16) float d_t[BB*CC*NPOS];          // conv+relu output, 64 MB
__device__ __align__(16) float d_scores[BB*NANCH];       // 2.25 MB
__device__ __align__(16) float d_deltas[BB*NANCH*4];     // 9 MB
__device__ __align__(16) float d_wt[4*32*72*64];         // transposed conv weights
__device__ unsigned int d_hist[BB][BINS];
__device__ int d_thrbin[BB];
__device__ int d_candcnt[BB];
__device__ unsigned long long d_cand[BB][CAP];
__device__ __align__(16) float d_boxes[BB][PRE_K*4];
__device__ unsigned int d_mask[BB][PRE_K*NMS_WORDS];

// anchor half-sizes, a = scale_idx*3 + ratio_idx, computed in double then fp32
__constant__ float c_hw[9] = {
    45.25483399593904f,  64.0f, 90.50966799187808f,
    90.50966799187808f, 128.0f, 181.01933598375617f,
    181.01933598375617f,256.0f, 362.03867196751233f};
__constant__ float c_hh[9] = {
    90.50966799187808f,  64.0f, 45.25483399593904f,
    181.01933598375617f,128.0f, 90.50966799187808f,
    362.03867196751233f,256.0f, 181.01933598375617f};

// smem layouts (floats)
#define CONV_SA_STAGE (8*18*18)            // 2592 floats per stage
#define CONV_SB_STAGE (72*64)              // 4608 floats per stage
#define CONV_SMEM_BYTES ((2*CONV_SA_STAGE + 2*CONV_SB_STAGE)*4)   // 57600
#define HEADS_SWC   0                       // 9*256 floats
#define HEADS_SWB   (9*256)                 // 36*256 floats
#define HEADS_SBC   (HEADS_SWB + 36*256)    // 9 floats
#define HEADS_SBB   (HEADS_SBC + 12)        // 36 floats (padded start)
#define HEADS_HIST  (HEADS_SBB + 36)        // 4096 uints
#define HEADS_SMEM_BYTES ((HEADS_HIST + BINS)*4)                  // 62660

// ---------------- packed f32x2 helpers (Blackwell) --------------------------
__device__ __forceinline__ u64 pack2(float x) {
    u64 r;
    asm("mov.b64 %0, {%1, %1};" : "=l"(r) : "f"(x));
    return r;
}
__device__ __forceinline__ u64 packab(float a, float b) {
    u64 r;
    asm("mov.b64 %0, {%1, %2};" : "=l"(r) : "f"(a), "f"(b));
    return r;
}
__device__ __forceinline__ void fma2(u64& d, u64 a, u64 b) {
    asm("fma.rn.f32x2 %0, %1, %2, %0;" : "+l"(d) : "l"(a), "l"(b));
}
__device__ __forceinline__ void unpack2(u64 a, float& lo, float& hi) {
    asm("mov.b64 {%0, %1}, %2;" : "=f"(lo), "=f"(hi) : "l"(a));
}

// ---------------- cp.async helpers ------------------------------------------
__device__ __forceinline__ void cp_async16(uint32_t s, const void* g) {
    asm volatile("cp.async.cg.shared.global [%0], [%1], 16;" :: "r"(s), "l"(g));
}
__device__ __forceinline__ void cp_async4z(uint32_t s, const void* g, bool ok) {
    int sz = ok ? 4 : 0;
    asm volatile("cp.async.ca.shared.global [%0], [%1], 4, %2;" :: "r"(s), "l"(g), "r"(sz));
}
#define CP_COMMIT()  asm volatile("cp.async.commit_group;" ::: "memory")
#define CP_WAIT1()   asm volatile("cp.async.wait_group 1;" ::: "memory")
#define CP_WAIT0()   asm volatile("cp.async.wait_group 0;" ::: "memory")

// ---------------- K0: weight transpose --------------------------------------
// d_wt[((g*32 + cb8)*72 + r)*64 + co] = w[(g*64+co)*2304 + cb8*72 + r]
__global__ void k_wt(const float* __restrict__ w) {
    int idx = blockIdx.x*1024 + threadIdx.x;
    if (idx >= 4*32*72*64) return;
    int co = idx & 63; int t = idx >> 6;
    int r = t % 72; t /= 72;
    int cb8 = t & 31; int g = t >> 5;
    d_wt[idx] = w[(g*64 + co)*2304 + cb8*72 + r];
}

// ---------------- K1: 3x3 conv (256->256) + ReLU, f32x2 + cp.async pipeline -
// grid (8,8,16): x=tile-x(16px), y=tile-y(16px), z = b*4 + co_group(64ch)
// block 256 threads: thread = pg(0..31)*8 + cg(0..7)
__global__ __launch_bounds__(256, 2)
void k_conv3(const float* __restrict__ f, const float* __restrict__ bias)
{
    extern __shared__ __align__(16) float smem[];
    float* sA = smem;                                   // 2 stages x 2592 floats
    float* sB = smem + 2*CONV_SA_STAGE;                 // 2 stages x 4608 floats

    const int tid = threadIdx.x;
    const int pg = tid >> 3, cg = tid & 7;
    const int pr = pg >> 1, pc = (pg & 1) * 8;
    const int b = blockIdx.z >> 2;
    const int g = blockIdx.z & 3;               // co group (64 channels)
    const int co_base = g * 64;
    const int x0 = blockIdx.x * 16, y0 = blockIdx.y * 16;

    const uint32_t sA0 = (uint32_t)__cvta_generic_to_shared(sA);
    const uint32_t sB0 = (uint32_t)__cvta_generic_to_shared(sB);

    u64 acc2[8][4];
    #pragma unroll
    for (int m = 0; m < 8; m++)
        #pragma unroll
        for (int jp = 0; jp < 4; jp++) acc2[m][jp] = 0ULL;

    // ---- async stage loader ----
    auto load_stage = [&](int st, int cb8) {
        const uint32_t sa = sA0 + st * (CONV_SA_STAGE*4);
        // halo: 8ci x 18 x 18 floats, 4B cp.async with zero-fill
        for (int e = tid; e < 8*18*18; e += 256) {
            int ci = e / 324; int rem = e - ci*324;
            int yy = rem / 18; int xx = rem - yy*18;
            int gy = y0 + yy - 1, gx = x0 + xx - 1;
            bool ok = (gy >= 0 && gy < 128 && gx >= 0 && gx < 128);
            int cy = gy < 0 ? 0 : (gy > 127 ? 127 : gy);
            int cx = gx < 0 ? 0 : (gx > 127 ? 127 : gx);
            cp_async4z(sa + e*4, &f[((b*256 + cb8*8 + ci)*128 + cy)*128 + cx], ok);
        }
        // weights: contiguous 72*64 floats from transposed layout, 16B chunks
        const float* ws = &d_wt[((g*32 + cb8)*72)*64];
        const uint32_t sb = sB0 + st * (CONV_SB_STAGE*4);
        for (int e = tid*4; e < 72*64; e += 1024)
            cp_async16(sb + e*4, ws + e);
    };

    load_stage(0, 0);
    CP_COMMIT();

    for (int cb8 = 0; cb8 < 32; cb8++) {
        const int cur = cb8 & 1;
        if (cb8 + 1 < 32) {
            load_stage(cur ^ 1, cb8 + 1);
            CP_COMMIT();
            CP_WAIT1();
        } else {
            CP_WAIT0();
        }
        __syncthreads();

        const float* sAc = sA + cur*CONV_SA_STAGE;
        const float* sBc = sB + cur*CONV_SB_STAGE;

        #pragma unroll
        for (int ci = 0; ci < 8; ci++) {
            #pragma unroll
            for (int ky = 0; ky < 3; ky++) {
                u64 aw[10];
                #pragma unroll
                for (int m = 0; m < 10; m++)
                    aw[m] = pack2(sAc[ci*324 + (pr + ky)*18 + pc + m]);
                #pragma unroll
                for (int kx = 0; kx < 3; kx++) {
                    const int kk = ci*9 + ky*3 + kx;
                    const ulonglong2 b01 = *(const ulonglong2*)&sBc[kk*64 + cg*8];
                    const ulonglong2 b23 = *(const ulonglong2*)&sBc[kk*64 + cg*8 + 4];
                    #pragma unroll
                    for (int m = 0; m < 8; m++) {
                        fma2(acc2[m][0], aw[kx + m], b01.x);
                        fma2(acc2[m][1], aw[kx + m], b01.y);
                        fma2(acc2[m][2], aw[kx + m], b23.x);
                        fma2(acc2[m][3], aw[kx + m], b23.y);
                    }
                }
            }
        }
        __syncthreads();
    }

    // epilogue: unpack, +bias, relu, vectorized store
    #pragma unroll
    for (int jp = 0; jp < 4; jp++) {
        const int co0 = co_base + cg*8 + jp*2;
        const float b0 = bias[co0], b1 = bias[co0 + 1];
        float v0[8], v1[8];
        #pragma unroll
        for (int m = 0; m < 8; m++) {
            float lo, hi;
            unpack2(acc2[m][jp], lo, hi);
            v0[m] = fmaxf(lo + b0, 0.f);
            v1[m] = fmaxf(hi + b1, 0.f);
        }
        float* p0 = &d_t[((b*256 + co0)*128 + (y0 + pr))*128 + (x0 + pc)];
        float* p1 = p0 + NPOS;
        *(float4*)p0       = make_float4(v0[0], v0[1], v0[2], v0[3]);
        *(float4*)(p0 + 4) = make_float4(v0[4], v0[5], v0[6], v0[7]);
        *(float4*)p1       = make_float4(v1[0], v1[1], v1[2], v1[3]);
        *(float4*)(p1 + 4) = make_float4(v1[4], v1[5], v1[6], v1[7]);
    }
}

// ---------------- selection helpers ----------------------------------------
__device__ __forceinline__ unsigned fkey(float s) {
    unsigned b = __float_as_uint(s);
    return (b & 0x80000000u) ? ~b : (b | 0x80000000u);  // monotone
}

// ---------------- K2: 1x1 heads (cls 9ch + bbox 36ch) + fused histogram ----
// grid (64, 4): 256 pixels per block, blockIdx.y = image
__global__ __launch_bounds__(256)
void k_heads(const float* __restrict__ cls_w, const float* __restrict__ cls_b,
             const float* __restrict__ bbox_w, const float* __restrict__ bbox_b)
{
    extern __shared__ __align__(16) float hsm[];
    float* swc = hsm + HEADS_SWC;                 // [9][256]
    float* swb = hsm + HEADS_SWB;                 // [36][256]
    float* sbc = hsm + HEADS_SBC;                 // [9]
    float* sbb = hsm + HEADS_SBB;                 // [36]
    unsigned* shist = (unsigned*)(hsm + HEADS_HIST);  // [4096]

    const int tid = threadIdx.x;
    const int b = blockIdx.y;
    const int p = blockIdx.x * 256 + tid;

    for (int e = tid; e < 9*256; e += 256)  swc[e] = cls_w[e];
    for (int e = tid; e < 36*256; e += 256) swb[e] = bbox_w[e];
    for (int e = tid; e < BINS; e += 256) shist[e] = 0u;
    if (tid < 9)  sbc[tid] = cls_b[tid];
    if (tid < 36) sbb[tid] = bbox_b[tid];
    __syncthreads();

    u64 as2[9], ad2[36];
    #pragma unroll
    for (int a = 0; a < 9; a++) as2[a] = 0ULL;
    #pragma unroll
    for (int d = 0; d < 36; d++) ad2[d] = 0ULL;

    const float* tp = d_t + (size_t)b*CC*NPOS + p;
    for (int c = 0; c < 256; c += 4) {
        const float t0 = tp[(c+0)*NPOS];
        const float t1 = tp[(c+1)*NPOS];
        const float t2 = tp[(c+2)*NPOS];
        const float t3 = tp[(c+3)*NPOS];
        const u64 t01 = packab(t0, t1);
        const u64 t23 = packab(t2, t3);
        #pragma unroll
        for (int a = 0; a < 9; a++) {
            const ulonglong2 wv = *(const ulonglong2*)&swc[a*256 + c];
            fma2(as2[a], t01, wv.x);
            fma2(as2[a], t23, wv.y);
        }
        #pragma unroll
        for (int d = 0; d < 36; d++) {
            const ulonglong2 wv = *(const ulonglong2*)&swb[d*256 + c];
            fma2(ad2[d], t01, wv.x);
            fma2(ad2[d], t23, wv.y);
        }
    }

    float* sp = d_scores + (size_t)b*NANCH + (size_t)p*9;
    #pragma unroll
    for (int a = 0; a < 9; a++) {
        float lo, hi; unpack2(as2[a], lo, hi);
        const float s = lo + hi + sbc[a];
        sp[a] = s;
        atomicAdd(&shist[fkey(s) >> BIN_SHIFT], 1u);
    }
    float* dp = d_deltas + ((size_t)b*NANCH + (size_t)p*9)*4;
    #pragma unroll
    for (int d = 0; d < 36; d++) {
        float lo, hi; unpack2(ad2[d], lo, hi);
        dp[d] = lo + hi + sbb[d];
    }
    __syncthreads();
    for (int e = tid; e < BINS; e += 256)
        if (shist[e]) atomicAdd(&d_hist[b][e], shist[e]);
}

__global__ void k_init() {
    int id = blockIdx.x * blockDim.x + threadIdx.x;
    if (id < BB*BINS) (&d_hist[0][0])[id] = 0u;
    if (id < BB) d_candcnt[id] = 0;
}

// suffix-sum over 4096 bins, pick highest bin with cum>=600
__global__ __launch_bounds__(1024) void k_thresh() {
    __shared__ unsigned suf[BINS + 1];
    const int tid = threadIdx.x;
    const int b = blockIdx.x;
    for (int e = tid; e < BINS; e += 1024) suf[e] = d_hist[b][e];
    if (tid == 0) suf[BINS] = 0u;
    __syncthreads();
    for (int off = 1; off < BINS; off <<= 1) {
        unsigned add[4];
        #pragma unroll
        for (int q = 0; q < 4; q++) {
            int i = tid + q*1024;
            add[q] = (i + off <= BINS) ? suf[i + off] : 0u;
        }
        __syncthreads();
        #pragma unroll
        for (int q = 0; q < 4; q++) suf[tid + q*1024] += add[q];
        __syncthreads();
    }
    #pragma unroll
    for (int q = 0; q < 4; q++) {
        int i = tid + q*1024;
        if (i < BINS && suf[i] >= PRE_K && suf[i+1] < PRE_K) d_thrbin[b] = i;
    }
}

__global__ void k_compact() {
    const int b = blockIdx.y;
    const int T = d_thrbin[b];
    const float* s = d_scores + (size_t)b*NANCH;
    for (unsigned i = blockIdx.x*blockDim.x + threadIdx.x; i < NANCH; i += gridDim.x*blockDim.x) {
        unsigned u = fkey(s[i]);
        if ((int)(u >> BIN_SHIFT) >= T) {
            int pos = atomicAdd(&d_candcnt[b], 1);
            if (pos < CAP)
                d_cand[b][pos] = ((unsigned long long)u << 32) | (unsigned)(~i);
        }
    }
}

__device__ __forceinline__ float read_dim(const void* p) {
    int i = *(const int*)p;
    float f = __int_as_float(i);
    return (i > 0 && i < (1 << 20)) ? (float)i : f;
}

// per-image: bitonic sort candidates desc by (score, then lower idx), decode top-600
__global__ __launch_bounds__(1024) void k_sortdecode(const void* ph, const void* pw) {
    __shared__ unsigned long long key[CAP];
    const int b = blockIdx.x;
    const int tid = threadIdx.x;
    int n = d_candcnt[b]; if (n > CAP) n = CAP;
    for (int e = tid; e < CAP; e += 1024) key[e] = (e < n) ? d_cand[b][e] : 0ULL;
    __syncthreads();

    for (int k = 2; k <= CAP; k <<= 1) {
        for (int j = k >> 1; j > 0; j >>= 1) {
            const int t = tid;
            const int i = ((t & ~(j - 1)) << 1) | (t & (j - 1));
            const int ixj = i | j;
            unsigned long long a = key[i], c = key[ixj];
            const bool up = ((i & k) == 0);
            if (up ? (a < c) : (a > c)) { key[i] = c; key[ixj] = a; }
            __syncthreads();
        }
    }

    if (tid < PRE_K) {
        const float img_h = read_dim(ph);
        const float img_w = read_dim(pw);
        const unsigned idx = ~(unsigned)(key[tid] & 0xFFFFFFFFULL);
        const int p = idx / 9, a = idx - 9*p;
        const float gx = (float)(p & 127) * 16.0f;
        const float gy = (float)(p >> 7) * 16.0f;
        const float hw = c_hw[a], hh = c_hh[a];
        const float x1 = gx - hw, y1 = gy - hh, x2 = gx + hw, y2 = gy + hh;
        const float w = x2 - x1, h = y2 - y1;
        const float cx = x1 + 0.5f*w, cy = y1 + 0.5f*h;
        const float4 dd = *(const float4*)&d_deltas[((size_t)b*NANCH + idx)*4];
        const float pcx = cx + dd.x * w;
        const float pcy = cy + dd.y * h;
        const float pw2 = w * expf(dd.z);
        const float ph2 = h * expf(dd.w);
        float4 o;
        o.x = fminf(fmaxf(pcx - 0.5f*pw2, 0.f), img_w);
        o.y = fminf(fmaxf(pcy - 0.5f*ph2, 0.f), img_h);
        o.z = fminf(fmaxf(pcx + 0.5f*pw2, 0.f), img_w);
        o.w = fminf(fmaxf(pcy + 0.5f*ph2, 0.f), img_h);
        *(float4*)&d_boxes[b][tid*4] = o;
    }
}

// 600x600 IoU suppression bitmask (j>i direction)
__global__ void k_mask() {
    const int id = blockIdx.x*blockDim.x + threadIdx.x;
    const int b = blockIdx.y;
    if (id >= PRE_K*NMS_WORDS) return;
    const int i = id / NMS_WORDS, wrd = id - i*NMS_WORDS;
    const float4 bi = *(const float4*)&d_boxes[b][i*4];
    const float areai = (bi.z - bi.x) * (bi.w - bi.y);
    unsigned m = 0u;
    const int j0 = wrd * 32;
    #pragma unroll 4
    for (int jj = 0; jj < 32; jj++) {
        const int j = j0 + jj;
        if (j > i && j < PRE_K) {
            const float4 bj = *(const float4*)&d_boxes[b][j*4];
            const float areaj = (bj.z - bj.x) * (bj.w - bj.y);
            const float xx1 = fmaxf(bi.x, bj.x), yy1 = fmaxf(bi.y, bj.y);
            const float xx2 = fminf(bi.z, bj.z), yy2 = fminf(bi.w, bj.w);
            const float inter = fmaxf(xx2 - xx1, 0.f) * fmaxf(yy2 - yy1, 0.f);
            const float iou = inter / (areai + areaj - inter);
            if (iou > 0.7f) m |= (1u << jj);
        }
    }
    d_mask[b][id] = m;
}

// serial suppression pass (single warp) + emit first 100 kept boxes
__global__ __launch_bounds__(128) void k_nms_out(float* __restrict__ out) {
    __shared__ unsigned smask[PRE_K*NMS_WORDS];
    __shared__ unsigned skeep[NMS_WORDS];
    __shared__ int s_sel[POST_K];
    __shared__ int s_cnt;
    const int b = blockIdx.x;
    const int tid = threadIdx.x;
    for (int e = tid; e < PRE_K*NMS_WORDS; e += 128) smask[e] = d_mask[b][e];
    __syncthreads();

    if (tid < 32) {
        unsigned rm = 0u;
        for (int i = 0; i < PRE_K; i++) {
            const unsigned wb = __shfl_sync(0xFFFFFFFFu, rm, i >> 5);
            if (!((wb >> (i & 31)) & 1u)) {
                if (tid < NMS_WORDS) rm |= smask[i*NMS_WORDS + tid];
            }
        }
        if (tid < NMS_WORDS) skeep[tid] = rm;
    }
    __syncthreads();
    if (tid == 0) {
        int cnt = 0;
        for (int j = 0; j < PRE_K && cnt < POST_K; j++)
            if (!((skeep[j >> 5] >> (j & 31)) & 1u)) s_sel[cnt++] = j;
        s_cnt = cnt;
    }
    __syncthreads();
    const int cnt = s_cnt;
    for (int k = tid; k < POST_K; k += 128) {
        float4 v = make_float4(0.f, 0.f, 0.f, 0.f);
        if (k < cnt) v = *(const float4*)&d_boxes[b][s_sel[k]*4];
        *(float4*)&out[(b*POST_K + k)*4] = v;
    }
}

// ---------------- launch ----------------------------------------------------
extern "C" void kernel_launch(void* const* d_in, const int* in_sizes, int n_in,
                              void* d_out, int out_size)
{
    const float* feats  = (const float*)d_in[0];
    const float* conv_w = (const float*)d_in[1];
    const float* conv_b = (const float*)d_in[2];
    const float* cls_w  = (const float*)d_in[3];
    const float* cls_b  = (const float*)d_in[4];
    const float* bbox_w = (const float*)d_in[5];
    const float* bbox_b = (const float*)d_in[6];
    const void*  ih     = d_in[7];
    const void*  iw     = d_in[8];

    // raise opt-in dynamic smem limits (host attribute calls; idempotent,
    // immediate, graph-capture safe — not stream ops)
    cudaFuncSetAttribute(k_conv3, cudaFuncAttributeMaxDynamicSharedMemorySize,
                         CONV_SMEM_BYTES);
    cudaFuncSetAttribute(k_heads, cudaFuncAttributeMaxDynamicSharedMemorySize,
                         HEADS_SMEM_BYTES);

    k_init<<<64, 256>>>();
    k_wt<<<576, 1024>>>(conv_w);
    k_conv3<<<dim3(8, 8, 16), 256, CONV_SMEM_BYTES>>>(feats, conv_b);
    k_heads<<<dim3(64, 4), 256, HEADS_SMEM_BYTES>>>(cls_w, cls_b, bbox_w, bbox_b);
    k_thresh<<<4, 1024>>>();
    k_compact<<<dim3(64, 4), 256>>>();
    k_sortdecode<<<4, 1024>>>(ih, iw);
    k_mask<<<dim3((PRE_K*NMS_WORDS + 255)/256, 4), 256>>>();
    k_nms_out<<<4, 128>>>((float*)d_out);
}